// round 1
// baseline (speedup 1.0000x reference)
#include <cuda_runtime.h>
#include <math.h>

// Problem constants
#define NB 8
#define NT 1024
#define ND 512
#define NFF 2048
#define NH 8
#define NDH 64
#define MROWS (NB*NT)   // 8192

// ---------------- scratch (device globals; no allocation allowed) -----------
__device__ float g_qkv[(size_t)3*NB*NT*ND];          // (3,b,t,d)
__device__ float g_probs[(size_t)NB*NH*NT*NT];       // (b,h,q,k)  256 MB
__device__ float g_ctx[(size_t)NB*NT*ND];            // merged context / ff2
__device__ float g_tmp[(size_t)NB*NT*NFF];           // proj out / ff hidden
__device__ float g_x1[(size_t)NB*NT*ND];             // post-attn LN
__device__ float g_outv[(size_t)NB*NT*ND];           // layer1 output
__device__ float g_outl[(size_t)NB*NT*ND];           // layer2 output
__device__ float g_colsum[NB*NT];
__device__ int   g_ids[NB*NT];
__device__ float g_wl[NB*NT];

// ---------------- generic tiled GEMM: C = A(MxK) @ B(KxN) -------------------
// FUSE: 0 none, 1 relu
template<int FUSE>
__global__ void k_gemm(const float* __restrict__ A, const float* __restrict__ Bm,
                       float* __restrict__ C, int M, int N, int K) {
    __shared__ float As[16][68];   // transposed A tile: As[k][m]
    __shared__ float Bs[16][68];   // Bs[k][n]
    int tid = threadIdx.x;
    int tx = tid & 15, ty = tid >> 4;
    int row0 = blockIdx.y * 64, col0 = blockIdx.x * 64;
    float acc[4][4] = {};
    for (int k0 = 0; k0 < K; k0 += 16) {
        #pragma unroll
        for (int i = 0; i < 4; i++) {
            int idx = tid + i * 256;            // 0..1023
            int r = idx >> 4, c = idx & 15;     // A tile 64x16
            As[c][r] = A[(size_t)(row0 + r) * K + k0 + c];
            int rb = idx >> 6, cb = idx & 63;   // B tile 16x64
            Bs[rb][cb] = Bm[(size_t)(k0 + rb) * N + col0 + cb];
        }
        __syncthreads();
        #pragma unroll
        for (int kk = 0; kk < 16; kk++) {
            float a[4], b[4];
            #pragma unroll
            for (int i = 0; i < 4; i++) a[i] = As[kk][ty * 4 + i];
            #pragma unroll
            for (int j = 0; j < 4; j++) b[j] = Bs[kk][tx * 4 + j];
            #pragma unroll
            for (int i = 0; i < 4; i++)
                #pragma unroll
                for (int j = 0; j < 4; j++) acc[i][j] += a[i] * b[j];
        }
        __syncthreads();
    }
    #pragma unroll
    for (int i = 0; i < 4; i++)
        #pragma unroll
        for (int j = 0; j < 4; j++) {
            int r = row0 + ty * 4 + i, cc = col0 + tx * 4 + j;
            float v = acc[i][j];
            if (FUSE == 1) v = fmaxf(v, 0.f);
            C[(size_t)r * N + cc] = v;
        }
}

// ---------------- attention scores: S = Q K^T / 8 (+window mask) ------------
__global__ void k_scores(const float* __restrict__ qkv, const int* __restrict__ ids,
                         float* __restrict__ P) {
    int bh = blockIdx.z; int b = bh / NH, h = bh % NH;
    const float* Q = qkv + ((size_t)b * NT) * ND + h * NDH;                  // c=0
    const float* Kp = qkv + ((size_t)(NB + b) * NT) * ND + h * NDH;          // c=1
    __shared__ float Qs[64][NDH + 1];
    __shared__ float Ks[64][NDH + 1];
    int tid = threadIdx.x;
    int q0 = blockIdx.y * 64, k0 = blockIdx.x * 64;
    #pragma unroll
    for (int i = 0; i < 16; i++) {
        int idx = tid + i * 256; int r = idx >> 6, c = idx & 63;
        Qs[r][c] = Q[(size_t)(q0 + r) * ND + c];
        Ks[r][c] = Kp[(size_t)(k0 + r) * ND + c];
    }
    __syncthreads();
    int tx = tid & 15, ty = tid >> 4;
    float acc[4][4] = {};
    #pragma unroll
    for (int kk = 0; kk < NDH; kk++) {
        float a[4], bv[4];
        #pragma unroll
        for (int i = 0; i < 4; i++) a[i] = Qs[ty * 4 + i][kk];
        #pragma unroll
        for (int j = 0; j < 4; j++) bv[j] = Ks[tx * 4 + j][kk];
        #pragma unroll
        for (int i = 0; i < 4; i++)
            #pragma unroll
            for (int j = 0; j < 4; j++) acc[i][j] += a[i] * bv[j];
    }
    float* Pp = P + (size_t)bh * NT * NT;
    #pragma unroll
    for (int i = 0; i < 4; i++) {
        int q = q0 + ty * 4 + i;
        #pragma unroll
        for (int j = 0; j < 4; j++) {
            int k = k0 + tx * 4 + j;
            float s = acc[i][j] * 0.125f;
            if (ids && ids[b * NT + q] != ids[b * NT + k]) s = -1e30f;
            Pp[(size_t)q * NT + k] = s;
        }
    }
}

// ---------------- row softmax over T=1024 (in place) ------------------------
__global__ void k_softmax_rows(float* __restrict__ P) {
    size_t row = blockIdx.x;
    float* p = P + row * (size_t)NT;
    __shared__ float red[256];
    int tid = threadIdx.x;
    float v[4];
    float m = -1e30f;
    #pragma unroll
    for (int i = 0; i < 4; i++) { v[i] = p[tid + i * 256]; m = fmaxf(m, v[i]); }
    red[tid] = m; __syncthreads();
    for (int o = 128; o > 0; o >>= 1) { if (tid < o) red[tid] = fmaxf(red[tid], red[tid + o]); __syncthreads(); }
    m = red[0]; __syncthreads();
    float s = 0.f;
    #pragma unroll
    for (int i = 0; i < 4; i++) { v[i] = __expf(v[i] - m); s += v[i]; }
    red[tid] = s; __syncthreads();
    for (int o = 128; o > 0; o >>= 1) { if (tid < o) red[tid] += red[tid + o]; __syncthreads(); }
    float inv = 1.f / red[0];
    #pragma unroll
    for (int i = 0; i < 4; i++) p[tid + i * 256] = v[i] * inv;
}

__global__ void k_zero(float* p, int n) {
    int i = blockIdx.x * blockDim.x + threadIdx.x;
    if (i < n) p[i] = 0.f;
}

// colsum[b,k] += (1/H) * sum_q P[b,h,q,k]
__global__ void k_colsum(const float* __restrict__ P, float* __restrict__ colsum) {
    int bh = blockIdx.y; int b = bh / NH;
    int k = blockIdx.x * 256 + threadIdx.x;
    const float* p = P + (size_t)bh * NT * NT + k;
    float acc = 0.f;
    for (int q = 0; q < NT; q++) acc += p[(size_t)q * NT];
    atomicAdd(&colsum[b * NT + k], acc * (1.f / NH));
}

// ---------------- ctx = P @ V  (per b,h; N=64), merged output ---------------
__global__ void k_ctx(const float* __restrict__ P, const float* __restrict__ qkv,
                      float* __restrict__ C) {
    int bh = blockIdx.y; int b = bh / NH, h = bh % NH;
    const float* Pp = P + (size_t)bh * NT * NT;
    const float* V = qkv + ((size_t)(2 * NB + b) * NT) * ND + h * NDH;       // c=2
    int q0 = blockIdx.x * 64;
    __shared__ float Ps[64][33];
    __shared__ float Vs[32][NDH + 1];
    int tid = threadIdx.x; int tx = tid & 15, ty = tid >> 4;
    float acc[4][4] = {};
    for (int k0 = 0; k0 < NT; k0 += 32) {
        #pragma unroll
        for (int i = 0; i < 8; i++) {
            int idx = tid + i * 256;
            int r = idx >> 5, c = idx & 31;          // 64x32
            Ps[r][c] = Pp[(size_t)(q0 + r) * NT + k0 + c];
            int rv = idx >> 6, cv = idx & 63;        // 32x64
            Vs[rv][cv] = V[(size_t)(k0 + rv) * ND + cv];
        }
        __syncthreads();
        #pragma unroll
        for (int kk = 0; kk < 32; kk++) {
            float a[4], bv[4];
            #pragma unroll
            for (int i = 0; i < 4; i++) a[i] = Ps[ty * 4 + i][kk];
            #pragma unroll
            for (int j = 0; j < 4; j++) bv[j] = Vs[kk][tx * 4 + j];
            #pragma unroll
            for (int i = 0; i < 4; i++)
                #pragma unroll
                for (int j = 0; j < 4; j++) acc[i][j] += a[i] * bv[j];
        }
        __syncthreads();
    }
    #pragma unroll
    for (int i = 0; i < 4; i++)
        #pragma unroll
        for (int j = 0; j < 4; j++)
            C[((size_t)b * NT + q0 + ty * 4 + i) * ND + h * NDH + tx * 4 + j] = acc[i][j];
}

// ---------------- residual add + layernorm ----------------------------------
__global__ void k_add_ln(const float* __restrict__ X, const float* __restrict__ Y,
                         float* __restrict__ O) {
    int row = blockIdx.x;
    const float* x = X + (size_t)row * ND;
    const float* y = Y + (size_t)row * ND;
    __shared__ float s[ND];
    __shared__ float red[256];
    int tid = threadIdx.x;
    float lsum = 0.f;
    for (int i = tid; i < ND; i += 256) { float v = x[i] + y[i]; s[i] = v; lsum += v; }
    red[tid] = lsum; __syncthreads();
    for (int o = 128; o > 0; o >>= 1) { if (tid < o) red[tid] += red[tid + o]; __syncthreads(); }
    float mean = red[0] * (1.f / ND); __syncthreads();
    float lv = 0.f;
    for (int i = tid; i < ND; i += 256) { float d = s[i] - mean; lv += d * d; }
    red[tid] = lv; __syncthreads();
    for (int o = 128; o > 0; o >>= 1) { if (tid < o) red[tid] += red[tid + o]; __syncthreads(); }
    float inv = rsqrtf(red[0] * (1.f / ND) + 1e-5f);
    for (int i = tid; i < ND; i += 256) O[(size_t)row * ND + i] = (s[i] - mean) * inv;
}

// ---------------- window ids: min-max normalize, threshold, run-length scan -
__global__ void k_windows(const float* __restrict__ colsum, int* __restrict__ ids) {
    int b = blockIdx.x;
    const float* w = colsum + b * NT;
    __shared__ float r1[256], r2[256];
    __shared__ unsigned char wb[NT];
    int tid = threadIdx.x;
    float mn = 1e30f, mx = -1e30f;
    for (int i = tid; i < NT; i += 256) { float v = w[i]; mn = fminf(mn, v); mx = fmaxf(mx, v); }
    r1[tid] = mn; r2[tid] = mx; __syncthreads();
    for (int o = 128; o > 0; o >>= 1) {
        if (tid < o) { r1[tid] = fminf(r1[tid], r1[tid + o]); r2[tid] = fmaxf(r2[tid], r2[tid + o]); }
        __syncthreads();
    }
    float wmin = r1[0];
    float denom = r2[0] - r1[0] + 1e-8f;
    for (int i = tid; i < NT; i += 256)
        wb[i] = ((w[i] - wmin) / denom >= 0.5f) ? 1 : 0;
    __syncthreads();
    if (tid == 0) {
        int* o = ids + b * NT;
        int cur = wb[0], start = 0, wid = 0;
        o[0] = 0;
        for (int t = 1; t < NT; t++) {
            int wt = wb[t];
            if (wt != cur) {
                if (start + 1 == t) { cur = wt; }              // length-1 run absorbed
                else { cur = wt; start = t; wid++; }           // close window
            }
            o[t] = wid;
        }
    }
}

// ---------------- per-batch softmax over T (for wl) -------------------------
__global__ void k_softmax_vec(const float* __restrict__ in, float* __restrict__ out) {
    int b = blockIdx.x;
    const float* p = in + b * NT;
    float* q = out + b * NT;
    __shared__ float red[256];
    int tid = threadIdx.x;
    float v[4];
    float m = -1e30f;
    #pragma unroll
    for (int i = 0; i < 4; i++) { v[i] = p[tid + i * 256]; m = fmaxf(m, v[i]); }
    red[tid] = m; __syncthreads();
    for (int o = 128; o > 0; o >>= 1) { if (tid < o) red[tid] = fmaxf(red[tid], red[tid + o]); __syncthreads(); }
    m = red[0]; __syncthreads();
    float s = 0.f;
    #pragma unroll
    for (int i = 0; i < 4; i++) { v[i] = __expf(v[i] - m); s += v[i]; }
    red[tid] = s; __syncthreads();
    for (int o = 128; o > 0; o >>= 1) { if (tid < o) red[tid] += red[tid + o]; __syncthreads(); }
    float inv = 1.f / red[0];
    #pragma unroll
    for (int i = 0; i < 4; i++) q[tid + i * 256] = v[i] * inv;
}

// ---------------- output assembly -------------------------------------------
// out[b, 0:T, :]   = 0 (word tokens base)
// out[b, T:2T, :]  = x
__global__ void k_out_base(const float* __restrict__ x, float* __restrict__ out) {
    size_t i = (size_t)blockIdx.x * blockDim.x + threadIdx.x;
    size_t total = (size_t)NB * 2 * NT * ND;
    if (i >= total) return;
    int d = (int)(i % ND);
    size_t r = i / ND;
    int row = (int)(r % (2 * NT));
    int b = (int)(r / (2 * NT));
    out[i] = (row < NT) ? 0.f : x[((size_t)b * NT + (row - NT)) * ND + d];
}

__global__ void k_scatter(const float* __restrict__ outl, const float* __restrict__ wl,
                          const int* __restrict__ ids, float* __restrict__ out) {
    int bt = blockIdx.x; int b = bt / NT;
    int w = ids[bt];
    float scale = wl[bt];
    float* dst = out + ((size_t)b * 2 * NT + w) * ND;
    const float* src = outl + (size_t)bt * ND;
    for (int d = threadIdx.x; d < ND; d += blockDim.x)
        atomicAdd(dst + d, src[d] * scale);
}

__global__ void k_winmap(const int* __restrict__ ids, float* __restrict__ out2) {
    size_t i = (size_t)blockIdx.x * blockDim.x + threadIdx.x;
    size_t total = (size_t)NB * NT * NT;
    if (i >= total) return;
    int t = (int)(i % NT);
    size_t r = i / NT;
    int w = (int)(r % NT);
    int b = (int)(r / NT);
    out2[i] = (ids[b * NT + t] == w) ? 1.f : 0.f;
}

// ---------------- host orchestration ----------------------------------------
static void run_layer(const float* xin, const float* qkvw, const float* outw,
                      const float* w1, const float* w2, const int* ids,
                      float* qkv, float* probs, float* ctx, float* tmp, float* x1,
                      float* xout, float* colsum) {
    // qkv projections (3 GEMMs, 8192x512x512 each)
    for (int c = 0; c < 3; c++)
        k_gemm<0><<<dim3(ND / 64, MROWS / 64), 256>>>(
            xin, qkvw + (size_t)c * ND * ND, qkv + (size_t)c * NB * NT * ND,
            MROWS, ND, ND);
    // scores (+mask), softmax, colsum
    k_scores<<<dim3(NT / 64, NT / 64, NB * NH), 256>>>(qkv, ids, probs);
    k_softmax_rows<<<NB * NH * NT, 256>>>(probs);
    k_zero<<<(NB * NT + 255) / 256, 256>>>(colsum, NB * NT);
    k_colsum<<<dim3(NT / 256, NB * NH), 256>>>(probs, colsum);
    // context + out projection + add&LN
    k_ctx<<<dim3(NT / 64, NB * NH), 256>>>(probs, qkv, ctx);
    k_gemm<0><<<dim3(ND / 64, MROWS / 64), 256>>>(ctx, outw, tmp, MROWS, ND, ND);
    k_add_ln<<<MROWS, 256>>>(xin, tmp, x1);
    // FFN
    k_gemm<1><<<dim3(NFF / 64, MROWS / 64), 256>>>(x1, w1, tmp, MROWS, NFF, ND);
    k_gemm<0><<<dim3(ND / 64, MROWS / 64), 256>>>(tmp, w2, ctx, MROWS, ND, NFF);
    k_add_ln<<<MROWS, 256>>>(x1, ctx, xout);
}

extern "C" void kernel_launch(void* const* d_in, const int* in_sizes, int n_in,
                              void* d_out, int out_size) {
    const float* x      = (const float*)d_in[0];
    const float* v_qkvw = (const float*)d_in[1];
    const float* v_outw = (const float*)d_in[2];
    const float* v_w1   = (const float*)d_in[3];
    const float* v_w2   = (const float*)d_in[4];
    const float* l_qkvw = (const float*)d_in[5];
    const float* l_outw = (const float*)d_in[6];
    const float* l_w1   = (const float*)d_in[7];
    const float* l_w2   = (const float*)d_in[8];

    float *qkv, *probs, *ctx, *tmp, *x1, *outv, *outl, *colsum, *wl;
    int* ids;
    cudaGetSymbolAddress((void**)&qkv,    g_qkv);
    cudaGetSymbolAddress((void**)&probs,  g_probs);
    cudaGetSymbolAddress((void**)&ctx,    g_ctx);
    cudaGetSymbolAddress((void**)&tmp,    g_tmp);
    cudaGetSymbolAddress((void**)&x1,     g_x1);
    cudaGetSymbolAddress((void**)&outv,   g_outv);
    cudaGetSymbolAddress((void**)&outl,   g_outl);
    cudaGetSymbolAddress((void**)&colsum, g_colsum);
    cudaGetSymbolAddress((void**)&ids,    g_ids);
    cudaGetSymbolAddress((void**)&wl,     g_wl);

    float* out = (float*)d_out;
    size_t sz1 = (size_t)NB * 2 * NT * ND;          // concat(word_tokens, x)
    size_t szwm = (size_t)NB * NT * NT;             // window_mapping

    // Layer 1 (vanilla)
    run_layer(x, v_qkvw, v_outw, v_w1, v_w2, nullptr,
              qkv, probs, ctx, tmp, x1, outv, colsum);
    // window ids from normalized per-key attention mass
    k_windows<<<NB, 256>>>(colsum, ids);
    // Layer 2 (block-diagonal windowed mask)
    run_layer(outv, l_qkvw, l_outw, l_w1, l_w2, ids,
              qkv, probs, ctx, tmp, x1, outl, colsum);
    // wl = softmax over keys of layer-2 head-averaged attention column sums
    k_softmax_vec<<<NB, 256>>>(colsum, wl);

    // Assemble outputs
    if ((size_t)out_size >= sz1) {
        k_out_base<<<(int)((sz1 + 255) / 256), 256>>>(x, out);
        k_scatter<<<NB * NT, 128>>>(outl, wl, ids, out);
    }
    if ((size_t)out_size >= sz1 + szwm) {
        k_winmap<<<(int)((szwm + 255) / 256), 256>>>(ids, out + sz1);
    }
}

// round 4
// speedup vs baseline: 1.5887x; 1.5887x over previous
#include <cuda_runtime.h>
#include <math.h>
#include <cstdint>

// Problem constants
#define NB 8
#define NT 1024
#define ND 512
#define NFF 2048
#define NH 8
#define NDH 64
#define MROWS (NB*NT)   // 8192

// ---------------- scratch (device globals; no allocation allowed) -----------
__device__ float g_qkv[(size_t)3*NB*NT*ND];          // (3,b,t,d)
__device__ float g_probs[(size_t)NB*NH*NT*NT];       // (b,h,q,k)  256 MB
__device__ float g_ctx[(size_t)NB*NT*ND];            // merged context / ff2
__device__ float g_tmp[(size_t)NB*NT*NFF];           // proj out / ff hidden
__device__ float g_x1[(size_t)NB*NT*ND];             // post-attn LN
__device__ float g_outv[(size_t)NB*NT*ND];           // layer1 output
__device__ float g_outl[(size_t)NB*NT*ND];           // layer2 output
__device__ float g_colsum[NB*NT];
__device__ int   g_ids[NB*NT];
__device__ float g_wl[NB*NT];
// transposed (and tf32-rounded) weights (Bt = B^T, [N,K] row-major)
__device__ float g_wT[5505024];

// offsets into g_wT (floats)
#define WT_VOUT 0
#define WT_VW1  (WT_VOUT + ND*ND)           // (FF,D)
#define WT_VW2  (WT_VW1 + NFF*ND)           // (D,FF)
#define WT_LQKV (WT_VW2 + ND*NFF)           // 3x(D,D)
#define WT_LOUT (WT_LQKV + 3*ND*ND)
#define WT_LW1  (WT_LOUT + ND*ND)
#define WT_LW2  (WT_LW1 + NFF*ND)

// ==================== small PTX helpers =====================================
__device__ __forceinline__ uint32_t smem_u32(const void* p) {
    uint32_t a;
    asm("{ .reg .u64 t; cvta.to.shared.u64 t, %1; cvt.u32.u64 %0, t; }" : "=r"(a) : "l"(p));
    return a;
}
__device__ __forceinline__ void cp_async16(uint32_t s, const void* g) {
    asm volatile("cp.async.cg.shared.global [%0], [%1], 16;" :: "r"(s), "l"(g));
}
__device__ __forceinline__ float tf32r(float x) {
    uint32_t u;
    asm("cvt.rna.tf32.f32 %0, %1;" : "=r"(u) : "f"(x));
    return __uint_as_float(u);
}

// =================== mma.sync tf32 GEMM: C = A(MxK) @ Bt(NxK)^T =============
// CTA 128x128, 256 threads (8 warps, 4x2), warp tile 32x64, BK=16,
// cp.async double-buffered smem, pitch 20 floats (conflict-free frags).
// Bt is pre-rounded to tf32; A fragments rounded at load (cvt.rna).
template<int FUSE>
__global__ void __launch_bounds__(256) k_mma_gemm(const float* __restrict__ A,
                                                  const float* __restrict__ Bt,
                                                  float* __restrict__ C,
                                                  int M, int N, int K) {
    const int PITCH = 20;
    __shared__ float sA[2][128 * PITCH];
    __shared__ float sB[2][128 * PITCH];

    const int tid = threadIdx.x;
    const int wid = tid >> 5, lane = tid & 31;
    const int row0 = blockIdx.y * 128, col0 = blockIdx.x * 128;
    const int m_base = (wid & 3) * 32;
    const int n_base = (wid >> 2) * 64;
    const int g = lane >> 2, c = lane & 3;

    const uint32_t aS = smem_u32(sA);
    const uint32_t bS = smem_u32(sB);

    float acc[2][8][4];
    #pragma unroll
    for (int mt = 0; mt < 2; mt++)
        #pragma unroll
        for (int nt = 0; nt < 8; nt++)
            #pragma unroll
            for (int i = 0; i < 4; i++) acc[mt][nt][i] = 0.f;

    // per-thread load slots: q = tid + i*256 in [0,512): r = q>>2 (row), c4 = q&3
    const int r_ld[2]  = { tid >> 2, (tid + 256) >> 2 };
    const int c4_ld[2] = { (tid & 3) * 4, (tid & 3) * 4 };

    auto load_chunk = [&](int buf, int k0) {
        #pragma unroll
        for (int i = 0; i < 2; i++) {
            int r = r_ld[i], c4 = c4_ld[i];
            uint32_t soff = (uint32_t)((buf * 128 * PITCH + r * PITCH + c4) * 4);
            cp_async16(aS + soff, A + (size_t)(row0 + r) * K + k0 + c4);
            cp_async16(bS + soff, Bt + (size_t)(col0 + r) * K + k0 + c4);
        }
        asm volatile("cp.async.commit_group;" ::: "memory");
    };

    const int nch = K >> 4;
    load_chunk(0, 0);

    for (int ch = 0; ch < nch; ch++) {
        asm volatile("cp.async.wait_group 0;" ::: "memory");
        __syncthreads();
        if (ch + 1 < nch) load_chunk((ch + 1) & 1, (ch + 1) << 4);

        const float* pa = &sA[ch & 1][0];
        const float* pb = &sB[ch & 1][0];
        #pragma unroll
        for (int ks = 0; ks < 2; ks++) {
            const int k = ks * 8;
            uint32_t afr[2][4];
            #pragma unroll
            for (int mt = 0; mt < 2; mt++) {
                const float* ap = pa + (m_base + mt * 16 + g) * PITCH + k + c;
                asm("cvt.rna.tf32.f32 %0, %1;" : "=r"(afr[mt][0]) : "f"(ap[0]));
                asm("cvt.rna.tf32.f32 %0, %1;" : "=r"(afr[mt][1]) : "f"(ap[8 * PITCH]));
                asm("cvt.rna.tf32.f32 %0, %1;" : "=r"(afr[mt][2]) : "f"(ap[4]));
                asm("cvt.rna.tf32.f32 %0, %1;" : "=r"(afr[mt][3]) : "f"(ap[8 * PITCH + 4]));
            }
            #pragma unroll
            for (int nt = 0; nt < 8; nt++) {
                const float* bp = pb + (n_base + nt * 8 + g) * PITCH + k + c;
                uint32_t b0 = __float_as_uint(bp[0]);
                uint32_t b1 = __float_as_uint(bp[4]);
                #pragma unroll
                for (int mt = 0; mt < 2; mt++) {
                    float* d = acc[mt][nt];
                    asm volatile(
                        "mma.sync.aligned.m16n8k8.row.col.f32.tf32.tf32.f32 "
                        "{%0,%1,%2,%3}, {%4,%5,%6,%7}, {%8,%9}, {%0,%1,%2,%3};"
                        : "+f"(d[0]), "+f"(d[1]), "+f"(d[2]), "+f"(d[3])
                        : "r"(afr[mt][0]), "r"(afr[mt][1]), "r"(afr[mt][2]), "r"(afr[mt][3]),
                          "r"(b0), "r"(b1));
                }
            }
        }
        __syncthreads();
    }

    // epilogue
    #pragma unroll
    for (int mt = 0; mt < 2; mt++) {
        int r = row0 + m_base + mt * 16 + g;
        #pragma unroll
        for (int nt = 0; nt < 8; nt++) {
            int cc = col0 + n_base + nt * 8 + 2 * c;
            float* d = acc[mt][nt];
            if (FUSE == 1) {
                d[0] = fmaxf(d[0], 0.f); d[1] = fmaxf(d[1], 0.f);
                d[2] = fmaxf(d[2], 0.f); d[3] = fmaxf(d[3], 0.f);
            }
            *reinterpret_cast<float2*>(C + (size_t)r * N + cc)       = make_float2(d[0], d[1]);
            *reinterpret_cast<float2*>(C + (size_t)(r + 8) * N + cc) = make_float2(d[2], d[3]);
        }
    }
}

// ---------------- weight transpose (+tf32 round): Bt[n*K+k] = B[k*N+n] ------
__global__ void k_transpose(const float* __restrict__ B, float* __restrict__ Bt,
                            int K, int N) {
    __shared__ float t[32][33];
    int n0 = blockIdx.x * 32, k0 = blockIdx.y * 32;
    int tx = threadIdx.x, ty = threadIdx.y;
    #pragma unroll
    for (int i = 0; i < 4; i++)
        t[ty + i * 8][tx] = B[(size_t)(k0 + ty + i * 8) * N + n0 + tx];
    __syncthreads();
    #pragma unroll
    for (int i = 0; i < 4; i++)
        Bt[(size_t)(n0 + ty + i * 8) * K + k0 + tx] = tf32r(t[tx][ty + i * 8]);
}

// ---------------- generic fp32 tiled GEMM (layer-1 qkv only) ---------------
template<int FUSE>
__global__ void k_gemm(const float* __restrict__ A, const float* __restrict__ Bm,
                       float* __restrict__ C, int M, int N, int K) {
    __shared__ float As[16][68];
    __shared__ float Bs[16][68];
    int tid = threadIdx.x;
    int tx = tid & 15, ty = tid >> 4;
    int row0 = blockIdx.y * 64, col0 = blockIdx.x * 64;
    float acc[4][4] = {};
    for (int k0 = 0; k0 < K; k0 += 16) {
        #pragma unroll
        for (int i = 0; i < 4; i++) {
            int idx = tid + i * 256;
            int r = idx >> 4, c = idx & 15;
            As[c][r] = A[(size_t)(row0 + r) * K + k0 + c];
            int rb = idx >> 6, cb = idx & 63;
            Bs[rb][cb] = Bm[(size_t)(k0 + rb) * N + col0 + cb];
        }
        __syncthreads();
        #pragma unroll
        for (int kk = 0; kk < 16; kk++) {
            float a[4], b[4];
            #pragma unroll
            for (int i = 0; i < 4; i++) a[i] = As[kk][ty * 4 + i];
            #pragma unroll
            for (int j = 0; j < 4; j++) b[j] = Bs[kk][tx * 4 + j];
            #pragma unroll
            for (int i = 0; i < 4; i++)
                #pragma unroll
                for (int j = 0; j < 4; j++) acc[i][j] += a[i] * b[j];
        }
        __syncthreads();
    }
    #pragma unroll
    for (int i = 0; i < 4; i++)
        #pragma unroll
        for (int j = 0; j < 4; j++) {
            int r = row0 + ty * 4 + i, cc = col0 + tx * 4 + j;
            float v = acc[i][j];
            if (FUSE == 1) v = fmaxf(v, 0.f);
            C[(size_t)r * N + cc] = v;
        }
}

// ---------------- attention scores: S = Q K^T / 8 (+window mask) ------------
__global__ void k_scores(const float* __restrict__ qkv, const int* __restrict__ ids,
                         float* __restrict__ P) {
    int bh = blockIdx.z; int b = bh / NH, h = bh % NH;
    const float* Q = qkv + ((size_t)b * NT) * ND + h * NDH;
    const float* Kp = qkv + ((size_t)(NB + b) * NT) * ND + h * NDH;
    __shared__ float Qs[64][NDH + 1];
    __shared__ float Ks[64][NDH + 1];
    int tid = threadIdx.x;
    int q0 = blockIdx.y * 64, k0 = blockIdx.x * 64;
    #pragma unroll
    for (int i = 0; i < 16; i++) {
        int idx = tid + i * 256; int r = idx >> 6, c = idx & 63;
        Qs[r][c] = Q[(size_t)(q0 + r) * ND + c];
        Ks[r][c] = Kp[(size_t)(k0 + r) * ND + c];
    }
    __syncthreads();
    int tx = tid & 15, ty = tid >> 4;
    float acc[4][4] = {};
    #pragma unroll
    for (int kk = 0; kk < NDH; kk++) {
        float a[4], bv[4];
        #pragma unroll
        for (int i = 0; i < 4; i++) a[i] = Qs[ty * 4 + i][kk];
        #pragma unroll
        for (int j = 0; j < 4; j++) bv[j] = Ks[tx * 4 + j][kk];
        #pragma unroll
        for (int i = 0; i < 4; i++)
            #pragma unroll
            for (int j = 0; j < 4; j++) acc[i][j] += a[i] * bv[j];
    }
    float* Pp = P + (size_t)bh * NT * NT;
    #pragma unroll
    for (int i = 0; i < 4; i++) {
        int q = q0 + ty * 4 + i;
        #pragma unroll
        for (int j = 0; j < 4; j++) {
            int k = k0 + tx * 4 + j;
            float s = acc[i][j] * 0.125f;
            if (ids && ids[b * NT + q] != ids[b * NT + k]) s = -1e30f;
            Pp[(size_t)q * NT + k] = s;
        }
    }
}

// ---------------- row softmax over T=1024 (in place) ------------------------
__global__ void k_softmax_rows(float* __restrict__ P) {
    size_t row = blockIdx.x;
    float* p = P + row * (size_t)NT;
    __shared__ float red[256];
    int tid = threadIdx.x;
    float v[4];
    float m = -1e30f;
    #pragma unroll
    for (int i = 0; i < 4; i++) { v[i] = p[tid + i * 256]; m = fmaxf(m, v[i]); }
    red[tid] = m; __syncthreads();
    for (int o = 128; o > 0; o >>= 1) { if (tid < o) red[tid] = fmaxf(red[tid], red[tid + o]); __syncthreads(); }
    m = red[0]; __syncthreads();
    float s = 0.f;
    #pragma unroll
    for (int i = 0; i < 4; i++) { v[i] = __expf(v[i] - m); s += v[i]; }
    red[tid] = s; __syncthreads();
    for (int o = 128; o > 0; o >>= 1) { if (tid < o) red[tid] += red[tid + o]; __syncthreads(); }
    float inv = 1.f / red[0];
    #pragma unroll
    for (int i = 0; i < 4; i++) p[tid + i * 256] = v[i] * inv;
}

__global__ void k_zero(float* p, int n) {
    int i = blockIdx.x * blockDim.x + threadIdx.x;
    if (i < n) p[i] = 0.f;
}

__global__ void k_colsum(const float* __restrict__ P, float* __restrict__ colsum) {
    int bh = blockIdx.y; int b = bh / NH;
    int k = blockIdx.x * 256 + threadIdx.x;
    const float* p = P + (size_t)bh * NT * NT + k;
    float acc = 0.f;
    for (int q = 0; q < NT; q++) acc += p[(size_t)q * NT];
    atomicAdd(&colsum[b * NT + k], acc * (1.f / NH));
}

// ---------------- ctx = P @ V  (per b,h; N=64), merged output ---------------
__global__ void k_ctx(const float* __restrict__ P, const float* __restrict__ qkv,
                      float* __restrict__ C) {
    int bh = blockIdx.y; int b = bh / NH, h = bh % NH;
    const float* Pp = P + (size_t)bh * NT * NT;
    const float* V = qkv + ((size_t)(2 * NB + b) * NT) * ND + h * NDH;
    int q0 = blockIdx.x * 64;
    __shared__ float Ps[64][33];
    __shared__ float Vs[32][NDH + 1];
    int tid = threadIdx.x; int tx = tid & 15, ty = tid >> 4;
    float acc[4][4] = {};
    for (int k0 = 0; k0 < NT; k0 += 32) {
        #pragma unroll
        for (int i = 0; i < 8; i++) {
            int idx = tid + i * 256;
            int r = idx >> 5, c = idx & 31;
            Ps[r][c] = Pp[(size_t)(q0 + r) * NT + k0 + c];
            int rv = idx >> 6, cv = idx & 63;
            Vs[rv][cv] = V[(size_t)(k0 + rv) * ND + cv];
        }
        __syncthreads();
        #pragma unroll
        for (int kk = 0; kk < 32; kk++) {
            float a[4], bv[4];
            #pragma unroll
            for (int i = 0; i < 4; i++) a[i] = Ps[ty * 4 + i][kk];
            #pragma unroll
            for (int j = 0; j < 4; j++) bv[j] = Vs[kk][tx * 4 + j];
            #pragma unroll
            for (int i = 0; i < 4; i++)
                #pragma unroll
                for (int j = 0; j < 4; j++) acc[i][j] += a[i] * bv[j];
        }
        __syncthreads();
    }
    #pragma unroll
    for (int i = 0; i < 4; i++)
        #pragma unroll
        for (int j = 0; j < 4; j++)
            C[((size_t)b * NT + q0 + ty * 4 + i) * ND + h * NDH + tx * 4 + j] = acc[i][j];
}

// ---------------- residual add + layernorm ----------------------------------
__global__ void k_add_ln(const float* __restrict__ X, const float* __restrict__ Y,
                         float* __restrict__ O) {
    int row = blockIdx.x;
    const float* x = X + (size_t)row * ND;
    const float* y = Y + (size_t)row * ND;
    __shared__ float s[ND];
    __shared__ float red[256];
    int tid = threadIdx.x;
    float lsum = 0.f;
    for (int i = tid; i < ND; i += 256) { float v = x[i] + y[i]; s[i] = v; lsum += v; }
    red[tid] = lsum; __syncthreads();
    for (int o = 128; o > 0; o >>= 1) { if (tid < o) red[tid] += red[tid + o]; __syncthreads(); }
    float mean = red[0] * (1.f / ND); __syncthreads();
    float lv = 0.f;
    for (int i = tid; i < ND; i += 256) { float d = s[i] - mean; lv += d * d; }
    red[tid] = lv; __syncthreads();
    for (int o = 128; o > 0; o >>= 1) { if (tid < o) red[tid] += red[tid + o]; __syncthreads(); }
    float inv = rsqrtf(red[0] * (1.f / ND) + 1e-5f);
    for (int i = tid; i < ND; i += 256) O[(size_t)row * ND + i] = (s[i] - mean) * inv;
}

// ---------------- window ids ------------------------------------------------
__global__ void k_windows(const float* __restrict__ colsum, int* __restrict__ ids) {
    int b = blockIdx.x;
    const float* w = colsum + b * NT;
    __shared__ float r1[256], r2[256];
    __shared__ unsigned char wb[NT];
    int tid = threadIdx.x;
    float mn = 1e30f, mx = -1e30f;
    for (int i = tid; i < NT; i += 256) { float v = w[i]; mn = fminf(mn, v); mx = fmaxf(mx, v); }
    r1[tid] = mn; r2[tid] = mx; __syncthreads();
    for (int o = 128; o > 0; o >>= 1) {
        if (tid < o) { r1[tid] = fminf(r1[tid], r1[tid + o]); r2[tid] = fmaxf(r2[tid], r2[tid + o]); }
        __syncthreads();
    }
    float wmin = r1[0];
    float denom = r2[0] - r1[0] + 1e-8f;
    for (int i = tid; i < NT; i += 256)
        wb[i] = ((w[i] - wmin) / denom >= 0.5f) ? 1 : 0;
    __syncthreads();
    if (tid == 0) {
        int* o = ids + b * NT;
        int cur = wb[0], start = 0, wid = 0;
        o[0] = 0;
        for (int t = 1; t < NT; t++) {
            int wt = wb[t];
            if (wt != cur) {
                if (start + 1 == t) { cur = wt; }
                else { cur = wt; start = t; wid++; }
            }
            o[t] = wid;
        }
    }
}

// ---------------- per-batch softmax over T (for wl) -------------------------
__global__ void k_softmax_vec(const float* __restrict__ in, float* __restrict__ out) {
    int b = blockIdx.x;
    const float* p = in + b * NT;
    float* q = out + b * NT;
    __shared__ float red[256];
    int tid = threadIdx.x;
    float v[4];
    float m = -1e30f;
    #pragma unroll
    for (int i = 0; i < 4; i++) { v[i] = p[tid + i * 256]; m = fmaxf(m, v[i]); }
    red[tid] = m; __syncthreads();
    for (int o = 128; o > 0; o >>= 1) { if (tid < o) red[tid] = fmaxf(red[tid], red[tid + o]); __syncthreads(); }
    m = red[0]; __syncthreads();
    float s = 0.f;
    #pragma unroll
    for (int i = 0; i < 4; i++) { v[i] = __expf(v[i] - m); s += v[i]; }
    red[tid] = s; __syncthreads();
    for (int o = 128; o > 0; o >>= 1) { if (tid < o) red[tid] += red[tid + o]; __syncthreads(); }
    float inv = 1.f / red[0];
    #pragma unroll
    for (int i = 0; i < 4; i++) q[tid + i * 256] = v[i] * inv;
}

// ---------------- output assembly -------------------------------------------
__global__ void k_out_base(const float* __restrict__ x, float* __restrict__ out) {
    size_t i = (size_t)blockIdx.x * blockDim.x + threadIdx.x;
    size_t total = (size_t)NB * 2 * NT * ND;
    if (i >= total) return;
    int d = (int)(i % ND);
    size_t r = i / ND;
    int row = (int)(r % (2 * NT));
    int b = (int)(r / (2 * NT));
    out[i] = (row < NT) ? 0.f : x[((size_t)b * NT + (row - NT)) * ND + d];
}

__global__ void k_scatter(const float* __restrict__ outl, const float* __restrict__ wl,
                          const int* __restrict__ ids, float* __restrict__ out) {
    int bt = blockIdx.x; int b = bt / NT;
    int w = ids[bt];
    float scale = wl[bt];
    float* dst = out + ((size_t)b * 2 * NT + w) * ND;
    const float* src = outl + (size_t)bt * ND;
    for (int d = threadIdx.x; d < ND; d += blockDim.x)
        atomicAdd(dst + d, src[d] * scale);
}

__global__ void k_winmap(const int* __restrict__ ids, float* __restrict__ out2) {
    size_t i = (size_t)blockIdx.x * blockDim.x + threadIdx.x;
    size_t total = (size_t)NB * NT * NT;
    if (i >= total) return;
    int t = (int)(i % NT);
    size_t r = i / NT;
    int w = (int)(r % NT);
    int b = (int)(r / NT);
    out2[i] = (ids[b * NT + t] == w) ? 1.f : 0.f;
}

// ---------------- host orchestration ----------------------------------------
static inline void tc_gemm(const float* A, const float* Bt, float* C,
                           int M, int N, int K, bool relu) {
    dim3 grid(N / 128, M / 128);
    if (relu) k_mma_gemm<1><<<grid, 256>>>(A, Bt, C, M, N, K);
    else      k_mma_gemm<0><<<grid, 256>>>(A, Bt, C, M, N, K);
}

static void run_attention(const float* qkv, const int* ids, float* probs,
                          float* ctx, float* colsum) {
    k_scores<<<dim3(NT / 64, NT / 64, NB * NH), 256>>>(qkv, ids, probs);
    k_softmax_rows<<<NB * NH * NT, 256>>>(probs);
    k_zero<<<(NB * NT + 255) / 256, 256>>>(colsum, NB * NT);
    k_colsum<<<dim3(NT / 256, NB * NH), 256>>>(probs, colsum);
    k_ctx<<<dim3(NT / 64, NB * NH), 256>>>(probs, qkv, ctx);
}

extern "C" void kernel_launch(void* const* d_in, const int* in_sizes, int n_in,
                              void* d_out, int out_size) {
    const float* x      = (const float*)d_in[0];
    const float* v_qkvw = (const float*)d_in[1];
    const float* v_outw = (const float*)d_in[2];
    const float* v_w1   = (const float*)d_in[3];
    const float* v_w2   = (const float*)d_in[4];
    const float* l_qkvw = (const float*)d_in[5];
    const float* l_outw = (const float*)d_in[6];
    const float* l_w1   = (const float*)d_in[7];
    const float* l_w2   = (const float*)d_in[8];

    float *qkv, *probs, *ctx, *tmp, *x1, *outv, *outl, *colsum, *wl, *wT;
    int* ids;
    cudaGetSymbolAddress((void**)&qkv,    g_qkv);
    cudaGetSymbolAddress((void**)&probs,  g_probs);
    cudaGetSymbolAddress((void**)&ctx,    g_ctx);
    cudaGetSymbolAddress((void**)&tmp,    g_tmp);
    cudaGetSymbolAddress((void**)&x1,     g_x1);
    cudaGetSymbolAddress((void**)&outv,   g_outv);
    cudaGetSymbolAddress((void**)&outl,   g_outl);
    cudaGetSymbolAddress((void**)&colsum, g_colsum);
    cudaGetSymbolAddress((void**)&ids,    g_ids);
    cudaGetSymbolAddress((void**)&wl,     g_wl);
    cudaGetSymbolAddress((void**)&wT,     g_wT);

    float* out = (float*)d_out;
    size_t sz1 = (size_t)NB * 2 * NT * ND;
    size_t szwm = (size_t)NB * NT * NT;

    // ---- transpose (+tf32 round) weights for mma GEMM (Bt = [N,K]) ----
    dim3 tb(32, 8);
    k_transpose<<<dim3(ND / 32, ND / 32), tb>>>(v_outw, wT + WT_VOUT, ND, ND);
    k_transpose<<<dim3(NFF / 32, ND / 32), tb>>>(v_w1, wT + WT_VW1, ND, NFF);
    k_transpose<<<dim3(ND / 32, NFF / 32), tb>>>(v_w2, wT + WT_VW2, NFF, ND);
    for (int c = 0; c < 3; c++)
        k_transpose<<<dim3(ND / 32, ND / 32), tb>>>(l_qkvw + (size_t)c * ND * ND,
                                                    wT + WT_LQKV + (size_t)c * ND * ND, ND, ND);
    k_transpose<<<dim3(ND / 32, ND / 32), tb>>>(l_outw, wT + WT_LOUT, ND, ND);
    k_transpose<<<dim3(NFF / 32, ND / 32), tb>>>(l_w1, wT + WT_LW1, ND, NFF);
    k_transpose<<<dim3(ND / 32, NFF / 32), tb>>>(l_w2, wT + WT_LW2, NFF, ND);

    // ---- Layer 1 (vanilla). qkv stays exact fp32: it determines the mask ----
    for (int c = 0; c < 3; c++)
        k_gemm<0><<<dim3(ND / 64, MROWS / 64), 256>>>(
            x, v_qkvw + (size_t)c * ND * ND, qkv + (size_t)c * NB * NT * ND,
            MROWS, ND, ND);
    run_attention(qkv, nullptr, probs, ctx, colsum);
    tc_gemm(ctx, wT + WT_VOUT, tmp, MROWS, ND, ND, false);
    k_add_ln<<<MROWS, 256>>>(x, tmp, x1);
    tc_gemm(x1, wT + WT_VW1, tmp, MROWS, NFF, ND, true);
    tc_gemm(tmp, wT + WT_VW2, ctx, MROWS, ND, NFF, false);
    k_add_ln<<<MROWS, 256>>>(x1, ctx, outv);

    // ---- window ids from layer-1 attention mass (exact fp32 path) ----
    k_windows<<<NB, 256>>>(colsum, ids);

    // ---- Layer 2 (windowed mask), big GEMMs in tf32 ----
    for (int c = 0; c < 3; c++)
        tc_gemm(outv, wT + WT_LQKV + (size_t)c * ND * ND,
                qkv + (size_t)c * NB * NT * ND, MROWS, ND, ND, false);
    run_attention(qkv, ids, probs, ctx, colsum);
    tc_gemm(ctx, wT + WT_LOUT, tmp, MROWS, ND, ND, false);
    k_add_ln<<<MROWS, 256>>>(outv, tmp, x1);
    tc_gemm(x1, wT + WT_LW1, tmp, MROWS, NFF, ND, true);
    tc_gemm(tmp, wT + WT_LW2, ctx, MROWS, ND, NFF, false);
    k_add_ln<<<MROWS, 256>>>(x1, ctx, outl);

    k_softmax_vec<<<NB, 256>>>(colsum, wl);

    // ---- Assemble outputs ----
    if ((size_t)out_size >= sz1) {
        k_out_base<<<(int)((sz1 + 255) / 256), 256>>>(x, out);
        k_scatter<<<NB * NT, 128>>>(outl, wl, ids, out);
    }
    if ((size_t)out_size >= sz1 + szwm) {
        k_winmap<<<(int)((szwm + 255) / 256), 256>>>(ids, out + sz1);
    }
}

// round 6
// speedup vs baseline: 2.2074x; 1.3894x over previous
#include <cuda_runtime.h>
#include <math.h>
#include <cstdint>

// Problem constants
#define NB 8
#define NT 1024
#define ND 512
#define NFF 2048
#define NH 8
#define NDH 64
#define MROWS (NB*NT)   // 8192

// ---------------- scratch (device globals; no allocation allowed) -----------
__device__ float g_qkv[(size_t)3*NB*NT*ND];          // (3,b,t,d)
__device__ float g_probs[(size_t)NB*NH*NT*NT];       // (b,h,q,k)  256 MB
__device__ float g_ctx[(size_t)NB*NT*ND];
__device__ float g_tmp[(size_t)NB*NT*NFF];
__device__ float g_x1[(size_t)NB*NT*ND];
__device__ float g_outv[(size_t)NB*NT*ND];
__device__ float g_outl[(size_t)NB*NT*ND];
__device__ float g_colsum[NB*NT];
__device__ int   g_ids[NB*NT];
__device__ float g_wl[NB*NT];
// transposed weights (tf32-rounded) for PREC=1 GEMMs
__device__ float g_wT[5505024];
// transposed raw (unrounded) layer-1 qkv weights for PREC=3 GEMM
__device__ float g_wTq[3*ND*ND];

#define WT_VOUT 0
#define WT_VW1  (WT_VOUT + ND*ND)
#define WT_VW2  (WT_VW1 + NFF*ND)
#define WT_LQKV (WT_VW2 + ND*NFF)
#define WT_LOUT (WT_LQKV + 3*ND*ND)
#define WT_LW1  (WT_LOUT + ND*ND)
#define WT_LW2  (WT_LW1 + NFF*ND)

// ==================== small PTX helpers =====================================
__device__ __forceinline__ uint32_t smem_u32(const void* p) {
    uint32_t a;
    asm("{ .reg .u64 t; cvta.to.shared.u64 t, %1; cvt.u32.u64 %0, t; }" : "=r"(a) : "l"(p));
    return a;
}
__device__ __forceinline__ void cp_async16(uint32_t s, const void* g) {
    asm volatile("cp.async.cg.shared.global [%0], [%1], 16;" :: "r"(s), "l"(g));
}
__device__ __forceinline__ uint32_t tf32u(float x) {
    uint32_t u;
    asm("cvt.rna.tf32.f32 %0, %1;" : "=r"(u) : "f"(x));
    return u;
}
__device__ __forceinline__ float tf32r(float x) { return __uint_as_float(tf32u(x)); }
__device__ __forceinline__ void mma_tf32(float* d, const uint32_t* a, uint32_t b0, uint32_t b1) {
    asm volatile(
        "mma.sync.aligned.m16n8k8.row.col.f32.tf32.tf32.f32 "
        "{%0,%1,%2,%3}, {%4,%5,%6,%7}, {%8,%9}, {%0,%1,%2,%3};"
        : "+f"(d[0]), "+f"(d[1]), "+f"(d[2]), "+f"(d[3])
        : "r"(a[0]), "r"(a[1]), "r"(a[2]), "r"(a[3]), "r"(b0), "r"(b1));
}

#define MMA_PITCH 20
#define MMA_SMEM_BYTES (2 * 3 * 128 * MMA_PITCH * 4)   // 61440

// =================== unified mma GEMM: C = A(MxK,lda) @ B(NxK,ldb)^T ========
// CTA 128x128, 256 threads (8 warps 4x2), warp tile 32x64, BK=16, 3-stage.
// EPI: 0 plain, 1 relu, 2 scores (x0.125 + optional window mask, batched z)
// PREC: 1 = tf32, 3 = 3xTF32 split (fp32-comparable accuracy)
template<int EPI, int PREC>
__global__ void __launch_bounds__(256) k_mma(const float* __restrict__ A,
                                             const float* __restrict__ B,
                                             float* __restrict__ C,
                                             int N, int K, int lda, int ldb, int ldc,
                                             const int* __restrict__ ids) {
    extern __shared__ float dsm[];
    float* sA = dsm;
    float* sB = dsm + 3 * 128 * MMA_PITCH;

    const int tid = threadIdx.x;
    const int wid = tid >> 5, lane = tid & 31;
    const int row0 = blockIdx.y * 128, col0 = blockIdx.x * 128;
    const int m_base = (wid & 3) * 32;
    const int n_base = (wid >> 2) * 64;
    const int g = lane >> 2, c = lane & 3;

    // batched offsets for scores
    const float* Ap = A;
    const float* Bp = B;
    float* Cp = C;
    const int* idb = nullptr;
    if (EPI == 2) {
        int bb = blockIdx.z >> 3, hh = blockIdx.z & 7;
        size_t off = (size_t)bb * NT * ND + hh * NDH;
        Ap = A + off; Bp = B + off;
        Cp = C + (size_t)blockIdx.z * NT * NT;
        if (ids) idb = ids + bb * NT;
    }

    const uint32_t aS = smem_u32(sA);
    const uint32_t bS = smem_u32(sB);

    float acc[2][8][4];
    #pragma unroll
    for (int mt = 0; mt < 2; mt++)
        #pragma unroll
        for (int nt = 0; nt < 8; nt++)
            #pragma unroll
            for (int i = 0; i < 4; i++) acc[mt][nt][i] = 0.f;

    auto load_chunk = [&](int buf, int k0) {
        #pragma unroll
        for (int i = 0; i < 2; i++) {
            int q = tid + i * 256;
            int r = q >> 2, c4 = (q & 3) * 4;
            uint32_t soff = (uint32_t)((buf * 128 * MMA_PITCH + r * MMA_PITCH + c4) * 4);
            cp_async16(aS + soff, Ap + (size_t)(row0 + r) * lda + k0 + c4);
            cp_async16(bS + soff, Bp + (size_t)(col0 + r) * ldb + k0 + c4);
        }
        asm volatile("cp.async.commit_group;" ::: "memory");
    };

    const int nch = K >> 4;
    load_chunk(0, 0);
    if (nch > 1) load_chunk(1, 16);

    for (int ch = 0; ch < nch; ch++) {
        if (ch + 1 < nch) { asm volatile("cp.async.wait_group 1;" ::: "memory"); }
        else              { asm volatile("cp.async.wait_group 0;" ::: "memory"); }
        __syncthreads();
        if (ch + 2 < nch) load_chunk((ch + 2) % 3, (ch + 2) << 4);

        const float* pa = sA + (ch % 3) * 128 * MMA_PITCH;
        const float* pb = sB + (ch % 3) * 128 * MMA_PITCH;
        #pragma unroll
        for (int ks = 0; ks < 2; ks++) {
            const int k = ks * 8;
            uint32_t ahi[2][4], alo[2][4];
            #pragma unroll
            for (int mt = 0; mt < 2; mt++) {
                const float* ap = pa + (m_base + mt * 16 + g) * MMA_PITCH + k + c;
                float ar[4] = { ap[0], ap[8 * MMA_PITCH], ap[4], ap[8 * MMA_PITCH + 4] };
                #pragma unroll
                for (int j = 0; j < 4; j++) {
                    ahi[mt][j] = tf32u(ar[j]);
                    if (PREC == 3)
                        alo[mt][j] = tf32u(ar[j] - __uint_as_float(ahi[mt][j]));
                }
            }
            #pragma unroll
            for (int nt = 0; nt < 8; nt++) {
                const float* bp = pb + (n_base + nt * 8 + g) * MMA_PITCH + k + c;
                float br0 = bp[0], br1 = bp[4];
                uint32_t bhi0, bhi1;
                if (EPI == 2 || PREC == 3) { bhi0 = tf32u(br0); bhi1 = tf32u(br1); }
                else { bhi0 = __float_as_uint(br0); bhi1 = __float_as_uint(br1); }
                uint32_t blo0 = 0, blo1 = 0;
                if (PREC == 3) {
                    blo0 = tf32u(br0 - __uint_as_float(bhi0));
                    blo1 = tf32u(br1 - __uint_as_float(bhi1));
                }
                #pragma unroll
                for (int mt = 0; mt < 2; mt++) {
                    if (PREC == 3) {
                        mma_tf32(acc[mt][nt], ahi[mt], blo0, blo1);
                        mma_tf32(acc[mt][nt], alo[mt], bhi0, bhi1);
                    }
                    mma_tf32(acc[mt][nt], ahi[mt], bhi0, bhi1);
                }
            }
        }
        __syncthreads();
    }

    // epilogue
    #pragma unroll
    for (int mt = 0; mt < 2; mt++) {
        int r = row0 + m_base + mt * 16 + g;
        int iq0 = 0, iq1 = 0;
        if (EPI == 2 && idb) { iq0 = idb[r]; iq1 = idb[r + 8]; }
        #pragma unroll
        for (int nt = 0; nt < 8; nt++) {
            int cc = col0 + n_base + nt * 8 + 2 * c;
            float* d = acc[mt][nt];
            if (EPI == 1) {
                d[0] = fmaxf(d[0], 0.f); d[1] = fmaxf(d[1], 0.f);
                d[2] = fmaxf(d[2], 0.f); d[3] = fmaxf(d[3], 0.f);
            }
            if (EPI == 2) {
                d[0] *= 0.125f; d[1] *= 0.125f; d[2] *= 0.125f; d[3] *= 0.125f;
                if (idb) {
                    int ik0 = idb[cc], ik1 = idb[cc + 1];
                    if (iq0 != ik0) d[0] = -1e30f;
                    if (iq0 != ik1) d[1] = -1e30f;
                    if (iq1 != ik0) d[2] = -1e30f;
                    if (iq1 != ik1) d[3] = -1e30f;
                }
            }
            *reinterpret_cast<float2*>(Cp + (size_t)r * ldc + cc)       = make_float2(d[0], d[1]);
            *reinterpret_cast<float2*>(Cp + (size_t)(r + 8) * ldc + cc) = make_float2(d[2], d[3]);
        }
    }
}

// =================== ctx mma: C[q,d] = sum_k P[q,k] V[k,d] (per b,h) ========
// CTA 128(M) x 64(N full head), 8 warps 4x2 (warp tile 32x32), BK=16, 3-stage.
#define VPITCH 72
__global__ void __launch_bounds__(256) k_mma_ctx(const float* __restrict__ P,
                                                 const float* __restrict__ qkv,
                                                 float* __restrict__ C) {
    __shared__ float sP[3][128 * MMA_PITCH];
    __shared__ float sV[3][16 * VPITCH];

    const int tid = threadIdx.x;
    const int wid = tid >> 5, lane = tid & 31;
    const int z = blockIdx.z;
    const int b = z >> 3, h = z & 7;
    const int row0 = blockIdx.x * 128;
    const int m_base = (wid & 3) * 32;
    const int n_base = (wid >> 2) * 32;
    const int g = lane >> 2, c = lane & 3;

    const float* Ap = P + (size_t)z * NT * NT;
    const float* Vp = qkv + (size_t)(2 * NB + b) * NT * ND + h * NDH;
    float* Cp = C + (size_t)b * NT * ND + h * NDH;

    const uint32_t pS = smem_u32(sP);
    const uint32_t vS = smem_u32(sV);

    float acc[2][4][4];
    #pragma unroll
    for (int mt = 0; mt < 2; mt++)
        #pragma unroll
        for (int nt = 0; nt < 4; nt++)
            #pragma unroll
            for (int i = 0; i < 4; i++) acc[mt][nt][i] = 0.f;

    auto load_chunk = [&](int buf, int k0) {
        #pragma unroll
        for (int i = 0; i < 2; i++) {
            int q = tid + i * 256;
            int r = q >> 2, c4 = (q & 3) * 4;
            uint32_t soff = (uint32_t)((buf * 128 * MMA_PITCH + r * MMA_PITCH + c4) * 4);
            cp_async16(pS + soff, Ap + (size_t)(row0 + r) * NT + k0 + c4);
        }
        {
            int r = tid >> 4, c4 = (tid & 15) * 4;
            uint32_t soff = (uint32_t)((buf * 16 * VPITCH + r * VPITCH + c4) * 4);
            cp_async16(vS + soff, Vp + (size_t)(k0 + r) * ND + c4);
        }
        asm volatile("cp.async.commit_group;" ::: "memory");
    };

    const int nch = NT >> 4;   // 64
    load_chunk(0, 0);
    load_chunk(1, 16);

    for (int ch = 0; ch < nch; ch++) {
        if (ch + 1 < nch) { asm volatile("cp.async.wait_group 1;" ::: "memory"); }
        else              { asm volatile("cp.async.wait_group 0;" ::: "memory"); }
        __syncthreads();
        if (ch + 2 < nch) load_chunk((ch + 2) % 3, (ch + 2) << 4);

        const float* pa = sP[ch % 3];
        const float* pv = sV[ch % 3];
        #pragma unroll
        for (int ks = 0; ks < 2; ks++) {
            const int k = ks * 8;
            uint32_t afr[2][4];
            #pragma unroll
            for (int mt = 0; mt < 2; mt++) {
                const float* ap = pa + (m_base + mt * 16 + g) * MMA_PITCH + k + c;
                afr[mt][0] = tf32u(ap[0]);
                afr[mt][1] = tf32u(ap[8 * MMA_PITCH]);
                afr[mt][2] = tf32u(ap[4]);
                afr[mt][3] = tf32u(ap[8 * MMA_PITCH + 4]);
            }
            #pragma unroll
            for (int nt = 0; nt < 4; nt++) {
                int n = n_base + nt * 8 + g;
                uint32_t b0 = tf32u(pv[(k + c) * VPITCH + n]);
                uint32_t b1 = tf32u(pv[(k + c + 4) * VPITCH + n]);
                #pragma unroll
                for (int mt = 0; mt < 2; mt++)
                    mma_tf32(acc[mt][nt], afr[mt], b0, b1);
            }
        }
        __syncthreads();
    }

    #pragma unroll
    for (int mt = 0; mt < 2; mt++) {
        int r = row0 + m_base + mt * 16 + g;
        #pragma unroll
        for (int nt = 0; nt < 4; nt++) {
            int cc = n_base + nt * 8 + 2 * c;
            float* d = acc[mt][nt];
            *reinterpret_cast<float2*>(Cp + (size_t)r * ND + cc)       = make_float2(d[0], d[1]);
            *reinterpret_cast<float2*>(Cp + (size_t)(r + 8) * ND + cc) = make_float2(d[2], d[3]);
        }
    }
}

// ---------------- weight transpose: Bt[n*K+k] = B[k*N+n] --------------------
template<int RND>
__global__ void k_transpose(const float* __restrict__ B, float* __restrict__ Bt,
                            int K, int N) {
    __shared__ float t[32][33];
    int n0 = blockIdx.x * 32, k0 = blockIdx.y * 32;
    int tx = threadIdx.x, ty = threadIdx.y;
    #pragma unroll
    for (int i = 0; i < 4; i++)
        t[ty + i * 8][tx] = B[(size_t)(k0 + ty + i * 8) * N + n0 + tx];
    __syncthreads();
    #pragma unroll
    for (int i = 0; i < 4; i++) {
        float v = t[tx][ty + i * 8];
        Bt[(size_t)(n0 + ty + i * 8) * K + k0 + tx] = RND ? tf32r(v) : v;
    }
}

// ---------------- row softmax over T=1024 (in place, vectorized) ------------
__global__ void k_softmax_rows(float* __restrict__ P) {
    size_t row = blockIdx.x;
    float4* p = reinterpret_cast<float4*>(P + row * (size_t)NT);
    __shared__ float red[256];
    int tid = threadIdx.x;
    float4 v = p[tid];
    float m = fmaxf(fmaxf(v.x, v.y), fmaxf(v.z, v.w));
    red[tid] = m; __syncthreads();
    for (int o = 128; o > 0; o >>= 1) { if (tid < o) red[tid] = fmaxf(red[tid], red[tid + o]); __syncthreads(); }
    m = red[0]; __syncthreads();
    v.x = __expf(v.x - m); v.y = __expf(v.y - m);
    v.z = __expf(v.z - m); v.w = __expf(v.w - m);
    red[tid] = v.x + v.y + v.z + v.w; __syncthreads();
    for (int o = 128; o > 0; o >>= 1) { if (tid < o) red[tid] += red[tid + o]; __syncthreads(); }
    float inv = 1.f / red[0];
    v.x *= inv; v.y *= inv; v.z *= inv; v.w *= inv;
    p[tid] = v;
}

__global__ void k_zero(float* p, int n) {
    int i = blockIdx.x * blockDim.x + threadIdx.x;
    if (i < n) p[i] = 0.f;
}

__global__ void k_colsum(const float* __restrict__ P, float* __restrict__ colsum) {
    int bh = blockIdx.y; int b = bh / NH;
    int k = blockIdx.x * 256 + threadIdx.x;
    const float* p = P + (size_t)bh * NT * NT + k;
    float acc = 0.f;
    #pragma unroll 8
    for (int q = 0; q < NT; q++) acc += p[(size_t)q * NT];
    atomicAdd(&colsum[b * NT + k], acc * (1.f / NH));
}

// ---------------- residual add + layernorm ----------------------------------
__global__ void k_add_ln(const float* __restrict__ X, const float* __restrict__ Y,
                         float* __restrict__ O) {
    int row = blockIdx.x;
    const float* x = X + (size_t)row * ND;
    const float* y = Y + (size_t)row * ND;
    __shared__ float s[ND];
    __shared__ float red[256];
    int tid = threadIdx.x;
    float lsum = 0.f;
    for (int i = tid; i < ND; i += 256) { float v = x[i] + y[i]; s[i] = v; lsum += v; }
    red[tid] = lsum; __syncthreads();
    for (int o = 128; o > 0; o >>= 1) { if (tid < o) red[tid] += red[tid + o]; __syncthreads(); }
    float mean = red[0] * (1.f / ND); __syncthreads();
    float lv = 0.f;
    for (int i = tid; i < ND; i += 256) { float d = s[i] - mean; lv += d * d; }
    red[tid] = lv; __syncthreads();
    for (int o = 128; o > 0; o >>= 1) { if (tid < o) red[tid] += red[tid + o]; __syncthreads(); }
    float inv = rsqrtf(red[0] * (1.f / ND) + 1e-5f);
    for (int i = tid; i < ND; i += 256) O[(size_t)row * ND + i] = (s[i] - mean) * inv;
}

// ---------------- window ids ------------------------------------------------
__global__ void k_windows(const float* __restrict__ colsum, int* __restrict__ ids) {
    int b = blockIdx.x;
    const float* w = colsum + b * NT;
    __shared__ float r1[256], r2[256];
    __shared__ unsigned char wb[NT];
    int tid = threadIdx.x;
    float mn = 1e30f, mx = -1e30f;
    for (int i = tid; i < NT; i += 256) { float v = w[i]; mn = fminf(mn, v); mx = fmaxf(mx, v); }
    r1[tid] = mn; r2[tid] = mx; __syncthreads();
    for (int o = 128; o > 0; o >>= 1) {
        if (tid < o) { r1[tid] = fminf(r1[tid], r1[tid + o]); r2[tid] = fmaxf(r2[tid], r2[tid + o]); }
        __syncthreads();
    }
    float wmin = r1[0];
    float denom = r2[0] - r1[0] + 1e-8f;
    for (int i = tid; i < NT; i += 256)
        wb[i] = ((w[i] - wmin) / denom >= 0.5f) ? 1 : 0;
    __syncthreads();
    if (tid == 0) {
        int* o = ids + b * NT;
        int cur = wb[0], start = 0, wid = 0;
        o[0] = 0;
        for (int t = 1; t < NT; t++) {
            int wt = wb[t];
            if (wt != cur) {
                if (start + 1 == t) { cur = wt; }
                else { cur = wt; start = t; wid++; }
            }
            o[t] = wid;
        }
    }
}

// ---------------- per-batch softmax over T (for wl) -------------------------
__global__ void k_softmax_vec(const float* __restrict__ in, float* __restrict__ out) {
    int b = blockIdx.x;
    const float* p = in + b * NT;
    float* q = out + b * NT;
    __shared__ float red[256];
    int tid = threadIdx.x;
    float v[4];
    float m = -1e30f;
    #pragma unroll
    for (int i = 0; i < 4; i++) { v[i] = p[tid + i * 256]; m = fmaxf(m, v[i]); }
    red[tid] = m; __syncthreads();
    for (int o = 128; o > 0; o >>= 1) { if (tid < o) red[tid] = fmaxf(red[tid], red[tid + o]); __syncthreads(); }
    m = red[0]; __syncthreads();
    float s = 0.f;
    #pragma unroll
    for (int i = 0; i < 4; i++) { v[i] = __expf(v[i] - m); s += v[i]; }
    red[tid] = s; __syncthreads();
    for (int o = 128; o > 0; o >>= 1) { if (tid < o) red[tid] += red[tid + o]; __syncthreads(); }
    float inv = 1.f / red[0];
    #pragma unroll
    for (int i = 0; i < 4; i++) q[tid + i * 256] = v[i] * inv;
}

// ---------------- output assembly -------------------------------------------
__global__ void k_out_base(const float* __restrict__ x, float* __restrict__ out) {
    size_t i = (size_t)blockIdx.x * blockDim.x + threadIdx.x;
    size_t total = (size_t)NB * 2 * NT * ND;
    if (i >= total) return;
    int d = (int)(i % ND);
    size_t r = i / ND;
    int row = (int)(r % (2 * NT));
    int b = (int)(r / (2 * NT));
    out[i] = (row < NT) ? 0.f : x[((size_t)b * NT + (row - NT)) * ND + d];
}

__global__ void k_scatter(const float* __restrict__ outl, const float* __restrict__ wl,
                          const int* __restrict__ ids, float* __restrict__ out) {
    int bt = blockIdx.x; int b = bt / NT;
    int w = ids[bt];
    float scale = wl[bt];
    float* dst = out + ((size_t)b * 2 * NT + w) * ND;
    const float* src = outl + (size_t)bt * ND;
    for (int d = threadIdx.x; d < ND; d += blockDim.x)
        atomicAdd(dst + d, src[d] * scale);
}

__global__ void k_winmap(const int* __restrict__ ids, float* __restrict__ out2) {
    size_t i = (size_t)blockIdx.x * blockDim.x + threadIdx.x;
    size_t total = (size_t)NB * NT * NT;
    if (i >= total) return;
    int t = (int)(i % NT);
    size_t r = i / NT;
    int w = (int)(r % NT);
    int b = (int)(r / NT);
    out2[i] = (ids[b * NT + t] == w) ? 1.f : 0.f;
}

// ---------------- host orchestration ----------------------------------------
template<int EPI, int PREC>
static inline void launch_mma(const float* A, const float* B, float* C,
                              int M, int N, int K, int lda, int ldb, int ldc,
                              const int* ids, int zdim) {
    static bool attr_done = false;
    if (!attr_done) {
        cudaFuncSetAttribute(k_mma<EPI, PREC>,
                             cudaFuncAttributeMaxDynamicSharedMemorySize, MMA_SMEM_BYTES);
        attr_done = true;
    }
    dim3 grid(N / 128, M / 128, zdim);
    k_mma<EPI, PREC><<<grid, 256, MMA_SMEM_BYTES>>>(A, B, C, N, K, lda, ldb, ldc, ids);
}

extern "C" void kernel_launch(void* const* d_in, const int* in_sizes, int n_in,
                              void* d_out, int out_size) {
    const float* x      = (const float*)d_in[0];
    const float* v_qkvw = (const float*)d_in[1];
    const float* v_outw = (const float*)d_in[2];
    const float* v_w1   = (const float*)d_in[3];
    const float* v_w2   = (const float*)d_in[4];
    const float* l_qkvw = (const float*)d_in[5];
    const float* l_outw = (const float*)d_in[6];
    const float* l_w1   = (const float*)d_in[7];
    const float* l_w2   = (const float*)d_in[8];

    float *qkv, *probs, *ctx, *tmp, *x1, *outv, *outl, *colsum, *wl, *wT, *wTq;
    int* ids;
    cudaGetSymbolAddress((void**)&qkv,    g_qkv);
    cudaGetSymbolAddress((void**)&probs,  g_probs);
    cudaGetSymbolAddress((void**)&ctx,    g_ctx);
    cudaGetSymbolAddress((void**)&tmp,    g_tmp);
    cudaGetSymbolAddress((void**)&x1,     g_x1);
    cudaGetSymbolAddress((void**)&outv,   g_outv);
    cudaGetSymbolAddress((void**)&outl,   g_outl);
    cudaGetSymbolAddress((void**)&colsum, g_colsum);
    cudaGetSymbolAddress((void**)&ids,    g_ids);
    cudaGetSymbolAddress((void**)&wl,     g_wl);
    cudaGetSymbolAddress((void**)&wT,     g_wT);
    cudaGetSymbolAddress((void**)&wTq,    g_wTq);

    float* out = (float*)d_out;
    size_t sz1 = (size_t)NB * 2 * NT * ND;
    size_t szwm = (size_t)NB * NT * NT;

    // ---- weight transposes ----
    dim3 tb(32, 8);
    for (int c = 0; c < 3; c++)
        k_transpose<0><<<dim3(ND / 32, ND / 32), tb>>>(v_qkvw + (size_t)c * ND * ND,
                                                       wTq + (size_t)c * ND * ND, ND, ND);
    k_transpose<1><<<dim3(ND / 32, ND / 32), tb>>>(v_outw, wT + WT_VOUT, ND, ND);
    k_transpose<1><<<dim3(NFF / 32, ND / 32), tb>>>(v_w1, wT + WT_VW1, ND, NFF);
    k_transpose<1><<<dim3(ND / 32, NFF / 32), tb>>>(v_w2, wT + WT_VW2, NFF, ND);
    for (int c = 0; c < 3; c++)
        k_transpose<1><<<dim3(ND / 32, ND / 32), tb>>>(l_qkvw + (size_t)c * ND * ND,
                                                       wT + WT_LQKV + (size_t)c * ND * ND, ND, ND);
    k_transpose<1><<<dim3(ND / 32, ND / 32), tb>>>(l_outw, wT + WT_LOUT, ND, ND);
    k_transpose<1><<<dim3(NFF / 32, ND / 32), tb>>>(l_w1, wT + WT_LW1, ND, NFF);
    k_transpose<1><<<dim3(ND / 32, NFF / 32), tb>>>(l_w2, wT + WT_LW2, NFF, ND);

    // ---- Layer 1 (vanilla). Mask-critical path uses 3xTF32 split precision ----
    for (int c = 0; c < 3; c++)
        launch_mma<0, 3>(x, wTq + (size_t)c * ND * ND, qkv + (size_t)c * NB * NT * ND,
                         MROWS, ND, ND, ND, ND, ND, nullptr, 1);
    launch_mma<2, 3>(qkv, qkv + (size_t)NB * NT * ND, probs,
                     NT, NT, NDH, ND, ND, NT, nullptr, NB * NH);
    k_softmax_rows<<<NB * NH * NT, 256>>>(probs);
    k_zero<<<(NB * NT + 255) / 256, 256>>>(colsum, NB * NT);
    k_colsum<<<dim3(NT / 256, NB * NH), 256>>>(probs, colsum);
    k_mma_ctx<<<dim3(NT / 128, 1, NB * NH), 256>>>(probs, qkv, ctx);
    launch_mma<0, 1>(ctx, wT + WT_VOUT, tmp, MROWS, ND, ND, ND, ND, ND, nullptr, 1);
    k_add_ln<<<MROWS, 256>>>(x, tmp, x1);
    launch_mma<1, 1>(x1, wT + WT_VW1, tmp, MROWS, NFF, ND, ND, ND, NFF, nullptr, 1);
    launch_mma<0, 1>(tmp, wT + WT_VW2, ctx, MROWS, ND, NFF, NFF, NFF, ND, nullptr, 1);
    k_add_ln<<<MROWS, 256>>>(x1, ctx, outv);

    // ---- window ids (discrete decision; inputs computed at ~fp32 accuracy) ----
    k_windows<<<NB, 256>>>(colsum, ids);

    // ---- Layer 2 (windowed mask), plain tf32 ----
    for (int c = 0; c < 3; c++)
        launch_mma<0, 1>(outv, wT + WT_LQKV + (size_t)c * ND * ND,
                         qkv + (size_t)c * NB * NT * ND, MROWS, ND, ND, ND, ND, ND, nullptr, 1);
    launch_mma<2, 1>(qkv, qkv + (size_t)NB * NT * ND, probs,
                     NT, NT, NDH, ND, ND, NT, ids, NB * NH);
    k_softmax_rows<<<NB * NH * NT, 256>>>(probs);
    k_zero<<<(NB * NT + 255) / 256, 256>>>(colsum, NB * NT);
    k_colsum<<<dim3(NT / 256, NB * NH), 256>>>(probs, colsum);
    k_mma_ctx<<<dim3(NT / 128, 1, NB * NH), 256>>>(probs, qkv, ctx);
    launch_mma<0, 1>(ctx, wT + WT_LOUT, tmp, MROWS, ND, ND, ND, ND, ND, nullptr, 1);
    k_add_ln<<<MROWS, 256>>>(outv, tmp, x1);
    launch_mma<1, 1>(x1, wT + WT_LW1, tmp, MROWS, NFF, ND, ND, ND, NFF, nullptr, 1);
    launch_mma<0, 1>(tmp, wT + WT_LW2, ctx, MROWS, ND, NFF, NFF, NFF, ND, nullptr, 1);
    k_add_ln<<<MROWS, 256>>>(x1, ctx, outl);

    k_softmax_vec<<<NB, 256>>>(colsum, wl);

    // ---- Assemble outputs ----
    if ((size_t)out_size >= sz1) {
        k_out_base<<<(int)((sz1 + 255) / 256), 256>>>(x, out);
        k_scatter<<<NB * NT, 128>>>(outl, wl, ids, out);
    }
    if ((size_t)out_size >= sz1 + szwm) {
        k_winmap<<<(int)((szwm + 255) / 256), 256>>>(ids, out + sz1);
    }
}